// round 1
// baseline (speedup 1.0000x reference)
#include <cuda_runtime.h>
#include <math.h>

#define TOLC   0.01f
#define ALPHAC 0.1f
#define SLOPEC 0.01f
#define EPSC   1e-10f

constexpr int P  = 64;    // points per CTA
constexpr int T  = 256;   // threads per CTA
constexpr int ZS = 65;    // padded stride for 64-wide buffers (65 % 32 == 1 -> conflict free)
constexpr int HS = 129;   // padded stride for 128-wide buffers (129 % 32 == 1)

// shared layout (floats):
//  [0,128)    sd   (d = X - Xstable)
//  [128,256)  sx   (X)
//  [256,384)  sgv  (gradV)
//  [384,448)  sV
//  [448,512)  sgf
//  [512,...)  union region:
//     V phase:    sz1[64*65], sz2[64*65], sz3[64*65], sW[64*65]     (16640 floats)
//     fhat phase: shA[64*129], shB[64*129], sWf[64*129]             (24768 floats)
constexpr int SMEM_FLOATS = 512 + 3 * 64 * HS;
constexpr int SMEM_BYTES  = SMEM_FLOATS * 4;  // 101120 bytes

__device__ __forceinline__ float sr(float x)  { return x < 0.f ? 0.f : (x < 1.f ? 0.5f * x * x : x - 0.5f); }
__device__ __forceinline__ float srp(float x) { return x < 0.f ? 0.f : (x < 1.f ? x : 1.f); }
// derivative of smooth_relu recovered from its OUTPUT z = sr(a):
//  a<0 -> z=0 -> 0 ;  0<=a<1 -> z=a^2/2<0.5 -> a=sqrt(2z) ;  a>=1 -> z>=0.5 -> 1
__device__ __forceinline__ float srp_out(float z) { return z <= 0.f ? 0.f : (z < 0.5f ? sqrtf(2.f * z) : 1.f); }
__device__ __forceinline__ float lrelu(float x) { return x >= 0.f ? x : SLOPEC * x; }

__global__ __launch_bounds__(T, 2)
void icnn_kernel(const float* __restrict__ X,   const float* __restrict__ Xs,
                 const float* __restrict__ Vl1, const float* __restrict__ V2x,
                 const float* __restrict__ V2z, const float* __restrict__ V3x,
                 const float* __restrict__ V3z, const float* __restrict__ Vfx,
                 const float* __restrict__ Vfz,
                 const float* __restrict__ f1w, const float* __restrict__ f1b,
                 const float* __restrict__ f2w, const float* __restrict__ f2b,
                 const float* __restrict__ f3w, const float* __restrict__ f3b,
                 const float* __restrict__ f4w, const float* __restrict__ f4b,
                 const float* __restrict__ f5w, const float* __restrict__ f5b,
                 const float* __restrict__ ffw, const float* __restrict__ ffb,
                 float* __restrict__ out, int n)
{
    extern __shared__ float sm[];
    float* sd  = sm;
    float* sx  = sm + 128;
    float* sgv = sm + 256;
    float* sV  = sm + 384;
    float* sgf = sm + 448;
    float* u   = sm + 512;
    float* sz1 = u;
    float* sz2 = u + 64 * ZS;
    float* sz3 = u + 128 * ZS;
    float* sW  = u + 192 * ZS;
    float* shA = u;
    float* shB = u + 64 * HS;
    float* sWf = u + 128 * HS;

    const int t    = threadIdx.x;
    const int base = blockIdx.x * P;
    const int ty   = t >> 4;   // 0..15  -> point groups (p = ty + 16*pi)
    const int tx   = t & 15;   // 0..15  -> output groups (j = tx + 16*ji)

    // ---- load points ----
    for (int i = t; i < P * 2; i += T) {
        int p = i >> 1, c = i & 1;
        int gi = base + p; if (gi >= n) gi = n - 1;
        float xv = X[gi * 2 + c];
        float xs = Xs[gi * 2 + c];
        sx[i] = xv;
        sd[i] = xv - xs;
    }
    __syncthreads();

    // ---- V forward: z1 ----
    for (int i = t; i < P * 64; i += T) {
        int p = i >> 6, j = i & 63;
        float a = sd[p * 2] * Vl1[j * 2] + sd[p * 2 + 1] * Vl1[j * 2 + 1];
        sz1[p * ZS + j] = sr(a);
    }
    // stage V2z  (sW[j][k] row-major)
    for (int i = t; i < 64 * 64; i += T) sW[(i >> 6) * ZS + (i & 63)] = V2z[i];
    __syncthreads();

    // ---- z2 = sr(d@V2x^T + z1@V2z^T) ----
    {
        float acc[4][4];
        #pragma unroll
        for (int pi = 0; pi < 4; pi++) {
            int p = ty + 16 * pi;
            #pragma unroll
            for (int ji = 0; ji < 4; ji++) {
                int j = tx + 16 * ji;
                acc[pi][ji] = sd[p * 2] * V2x[j * 2] + sd[p * 2 + 1] * V2x[j * 2 + 1];
            }
        }
        #pragma unroll 4
        for (int k = 0; k < 64; k++) {
            float a[4], w[4];
            #pragma unroll
            for (int pi = 0; pi < 4; pi++) a[pi] = sz1[(ty + 16 * pi) * ZS + k];
            #pragma unroll
            for (int ji = 0; ji < 4; ji++) w[ji] = sW[(tx + 16 * ji) * ZS + k];
            #pragma unroll
            for (int pi = 0; pi < 4; pi++)
                #pragma unroll
                for (int ji = 0; ji < 4; ji++) acc[pi][ji] += a[pi] * w[ji];
        }
        #pragma unroll
        for (int pi = 0; pi < 4; pi++)
            #pragma unroll
            for (int ji = 0; ji < 4; ji++)
                sz2[(ty + 16 * pi) * ZS + tx + 16 * ji] = sr(acc[pi][ji]);
    }
    __syncthreads();
    // stage V3z
    for (int i = t; i < 64 * 64; i += T) sW[(i >> 6) * ZS + (i & 63)] = V3z[i];
    __syncthreads();

    // ---- z3 = sr(d@V3x^T + z2@V3z^T) ----
    {
        float acc[4][4];
        #pragma unroll
        for (int pi = 0; pi < 4; pi++) {
            int p = ty + 16 * pi;
            #pragma unroll
            for (int ji = 0; ji < 4; ji++) {
                int j = tx + 16 * ji;
                acc[pi][ji] = sd[p * 2] * V3x[j * 2] + sd[p * 2 + 1] * V3x[j * 2 + 1];
            }
        }
        #pragma unroll 4
        for (int k = 0; k < 64; k++) {
            float a[4], w[4];
            #pragma unroll
            for (int pi = 0; pi < 4; pi++) a[pi] = sz2[(ty + 16 * pi) * ZS + k];
            #pragma unroll
            for (int ji = 0; ji < 4; ji++) w[ji] = sW[(tx + 16 * ji) * ZS + k];
            #pragma unroll
            for (int pi = 0; pi < 4; pi++)
                #pragma unroll
                for (int ji = 0; ji < 4; ji++) acc[pi][ji] += a[pi] * w[ji];
        }
        #pragma unroll
        for (int pi = 0; pi < 4; pi++)
            #pragma unroll
            for (int ji = 0; ji < 4; ji++)
                sz3[(ty + 16 * pi) * ZS + tx + 16 * ji] = sr(acc[pi][ji]);
    }
    __syncthreads();   // sW (V3z) is kept for the backward pass

    // ---- zf, V, gf ----
    if (t < 64) {
        int p = t;
        float af = sd[p * 2] * Vfx[0] + sd[p * 2 + 1] * Vfx[1];
        #pragma unroll 4
        for (int k = 0; k < 64; k++) af += Vfz[k] * sz3[p * ZS + k];
        float zf = sr(af);
        sgf[p] = srp(zf) * srp(af);                       // dV/d(af)
        sV[p]  = sr(zf) + TOLC * (sd[p * 2] * sd[p * 2] + sd[p * 2 + 1] * sd[p * 2 + 1]);
    }
    __syncthreads();

    // ---- g_a3 = gf * Vfz * sr'(a3)  (in place over sz3) ----
    for (int i = t; i < P * 64; i += T) {
        int p = i >> 6, j = i & 63;
        float z = sz3[p * ZS + j];
        sz3[p * ZS + j] = sgf[p] * Vfz[j] * srp_out(z);
    }
    __syncthreads();

    // ---- g_a2 = (V3z^T @ g_a3) * sr'(a2)  (in place over sz2; sW holds V3z) ----
    {
        float acc[4][4] = {};
        #pragma unroll 4
        for (int k = 0; k < 64; k++) {
            float a[4], w[4];
            #pragma unroll
            for (int pi = 0; pi < 4; pi++) a[pi] = sz3[(ty + 16 * pi) * ZS + k];
            #pragma unroll
            for (int ji = 0; ji < 4; ji++) w[ji] = sW[k * ZS + tx + 16 * ji];
            #pragma unroll
            for (int pi = 0; pi < 4; pi++)
                #pragma unroll
                for (int ji = 0; ji < 4; ji++) acc[pi][ji] += a[pi] * w[ji];
        }
        #pragma unroll
        for (int pi = 0; pi < 4; pi++)
            #pragma unroll
            for (int ji = 0; ji < 4; ji++) {
                int p = ty + 16 * pi, j = tx + 16 * ji;
                float z = sz2[p * ZS + j];                // own element only -> no race
                sz2[p * ZS + j] = acc[pi][ji] * srp_out(z);
            }
    }
    __syncthreads();
    // restage V2z
    for (int i = t; i < 64 * 64; i += T) sW[(i >> 6) * ZS + (i & 63)] = V2z[i];
    __syncthreads();

    // ---- g_a1 = (V2z^T @ g_a2) * sr'(a1)  (in place over sz1) ----
    {
        float acc[4][4] = {};
        #pragma unroll 4
        for (int k = 0; k < 64; k++) {
            float a[4], w[4];
            #pragma unroll
            for (int pi = 0; pi < 4; pi++) a[pi] = sz2[(ty + 16 * pi) * ZS + k];
            #pragma unroll
            for (int ji = 0; ji < 4; ji++) w[ji] = sW[k * ZS + tx + 16 * ji];
            #pragma unroll
            for (int pi = 0; pi < 4; pi++)
                #pragma unroll
                for (int ji = 0; ji < 4; ji++) acc[pi][ji] += a[pi] * w[ji];
        }
        #pragma unroll
        for (int pi = 0; pi < 4; pi++)
            #pragma unroll
            for (int ji = 0; ji < 4; ji++) {
                int p = ty + 16 * pi, j = tx + 16 * ji;
                float z = sz1[p * ZS + j];
                sz1[p * ZS + j] = acc[pi][ji] * srp_out(z);
            }
    }
    __syncthreads();

    // ---- gradV[p][c] ----
    if (t < 128) {
        int p = t >> 1, c = t & 1;
        float acc = sgf[p] * Vfx[c] + 2.f * TOLC * sd[p * 2 + c];
        #pragma unroll 4
        for (int k = 0; k < 64; k++) {
            acc += sz3[p * ZS + k] * V3x[k * 2 + c];
            acc += sz2[p * ZS + k] * V2x[k * 2 + c];
            acc += sz1[p * ZS + k] * Vl1[k * 2 + c];
        }
        sgv[p * 2 + c] = acc;
    }
    __syncthreads();

    // ================= f_hat =================
    // layer 1
    for (int i = t; i < P * 128; i += T) {
        int p = i >> 7, j = i & 127;
        float a = sx[p * 2] * f1w[j * 2] + sx[p * 2 + 1] * f1w[j * 2 + 1] + f1b[j];
        shA[p * HS + j] = lrelu(a);
    }
    __syncthreads();

    const float* Ws[4] = { f2w, f3w, f4w, f5w };
    const float* Bs[4] = { f2b, f3b, f4b, f5b };
    float* hin = shA;
    float* hout = shB;

    for (int L = 0; L < 4; L++) {
        const float* Wg = Ws[L];
        const float* Bg = Bs[L];
        for (int c0 = 0; c0 < 128; c0 += 64) {
            // stage 64 output rows of W
            for (int i = t; i < 64 * 128; i += T)
                sWf[(i >> 7) * HS + (i & 127)] = Wg[(c0 + (i >> 7)) * 128 + (i & 127)];
            __syncthreads();

            float acc[4][4];
            #pragma unroll
            for (int pi = 0; pi < 4; pi++)
                #pragma unroll
                for (int ji = 0; ji < 4; ji++)
                    acc[pi][ji] = Bg[c0 + tx + 16 * ji];

            #pragma unroll 4
            for (int k = 0; k < 128; k++) {
                float a[4], w[4];
                #pragma unroll
                for (int pi = 0; pi < 4; pi++) a[pi] = hin[(ty + 16 * pi) * HS + k];
                #pragma unroll
                for (int ji = 0; ji < 4; ji++) w[ji] = sWf[(tx + 16 * ji) * HS + k];
                #pragma unroll
                for (int pi = 0; pi < 4; pi++)
                    #pragma unroll
                    for (int ji = 0; ji < 4; ji++) acc[pi][ji] += a[pi] * w[ji];
            }
            #pragma unroll
            for (int pi = 0; pi < 4; pi++)
                #pragma unroll
                for (int ji = 0; ji < 4; ji++)
                    hout[(ty + 16 * pi) * HS + c0 + tx + 16 * ji] = lrelu(acc[pi][ji]);
            __syncthreads();
        }
        float* tmp = hin; hin = hout; hout = tmp;
    }
    // after 4 swaps: final activations are in hin (== shA)

    // ---- final layer + projection ----
    if (t < 64) {
        int p = t;
        float fh0 = ffb[0], fh1 = ffb[1];
        #pragma unroll 4
        for (int k = 0; k < 128; k++) {
            float h = hin[p * HS + k];
            fh0 += h * ffw[k];
            fh1 += h * ffw[128 + k];
        }
        float g0 = sgv[p * 2], g1 = sgv[p * 2 + 1];
        float vn  = g0 * g0 + g1 * g1;
        float fhv = fh0 * g0 + fh1 * g1;
        float num = fhv + ALPHAC * sV[p];
        float fm  = (num > 0.f ? num : 0.f) / (vn + EPSC);
        int gi = base + p;
        if (gi < n) {
            out[gi * 2]     = fh0 - g0 * fm;
            out[gi * 2 + 1] = fh1 - g1 * fm;
        }
    }
}

extern "C" void kernel_launch(void* const* d_in, const int* in_sizes, int n_in,
                              void* d_out, int out_size)
{
    const float* X   = (const float*)d_in[0];
    const float* Xs  = (const float*)d_in[1];
    const float* Vl1 = (const float*)d_in[2];
    const float* V2x = (const float*)d_in[3];
    const float* V2z = (const float*)d_in[4];
    const float* V3x = (const float*)d_in[5];
    const float* V3z = (const float*)d_in[6];
    const float* Vfx = (const float*)d_in[7];
    const float* Vfz = (const float*)d_in[8];
    const float* f1w = (const float*)d_in[9];
    const float* f1b = (const float*)d_in[10];
    const float* f2w = (const float*)d_in[11];
    const float* f2b = (const float*)d_in[12];
    const float* f3w = (const float*)d_in[13];
    const float* f3b = (const float*)d_in[14];
    const float* f4w = (const float*)d_in[15];
    const float* f4b = (const float*)d_in[16];
    const float* f5w = (const float*)d_in[17];
    const float* f5b = (const float*)d_in[18];
    const float* ffw = (const float*)d_in[19];
    const float* ffb = (const float*)d_in[20];

    int n = in_sizes[0] / 2;
    int grid = (n + P - 1) / P;

    cudaFuncSetAttribute(icnn_kernel, cudaFuncAttributeMaxDynamicSharedMemorySize, SMEM_BYTES);

    icnn_kernel<<<grid, T, SMEM_BYTES>>>(
        X, Xs, Vl1, V2x, V2z, V3x, V3z, Vfx, Vfz,
        f1w, f1b, f2w, f2b, f3w, f3b, f4w, f4b, f5w, f5b, ffw, ffb,
        (float*)d_out, n);
}

// round 2
// speedup vs baseline: 1.0005x; 1.0005x over previous
#include <cuda_runtime.h>
#include <math.h>

#define TOLC   0.01f
#define ALPHAC 0.1f
#define SLOPEC 0.01f
#define EPSC   1e-10f

constexpr int P  = 64;    // points per CTA
constexpr int T  = 256;   // threads per CTA
constexpr int ZS = 65;    // padded stride for 64-wide buffers (65 % 32 == 1 -> conflict free)
constexpr int HS = 129;   // padded stride for 128-wide buffers (129 % 32 == 1)

// shared layout (floats):
//  [0,128)    sd   (d = X - Xstable)
//  [128,256)  sx   (X)
//  [256,384)  sgv  (gradV)
//  [384,448)  sV
//  [448,512)  sgf
//  [512,...)  union region:
//     V phase:    sz1[64*65], sz2[64*65], sz3[64*65], sW[64*65]     (16640 floats)
//     fhat phase: shA[64*129], shB[64*129], sWf[64*129]             (24768 floats)
constexpr int SMEM_FLOATS = 512 + 3 * 64 * HS;
constexpr int SMEM_BYTES  = SMEM_FLOATS * 4;  // 101120 bytes

__device__ __forceinline__ float sr(float x)  { return x < 0.f ? 0.f : (x < 1.f ? 0.5f * x * x : x - 0.5f); }
__device__ __forceinline__ float srp(float x) { return x < 0.f ? 0.f : (x < 1.f ? x : 1.f); }
// derivative of smooth_relu recovered from its OUTPUT z = sr(a):
//  a<0 -> z=0 -> 0 ;  0<=a<1 -> z=a^2/2<0.5 -> a=sqrt(2z) ;  a>=1 -> z>=0.5 -> 1
__device__ __forceinline__ float srp_out(float z) { return z <= 0.f ? 0.f : (z < 0.5f ? sqrtf(2.f * z) : 1.f); }
__device__ __forceinline__ float lrelu(float x) { return x >= 0.f ? x : SLOPEC * x; }

__global__ __launch_bounds__(T, 2)
void icnn_kernel(const float* __restrict__ X,   const float* __restrict__ Xs,
                 const float* __restrict__ Vl1, const float* __restrict__ V2x,
                 const float* __restrict__ V2z, const float* __restrict__ V3x,
                 const float* __restrict__ V3z, const float* __restrict__ Vfx,
                 const float* __restrict__ Vfz,
                 const float* __restrict__ f1w, const float* __restrict__ f1b,
                 const float* __restrict__ f2w, const float* __restrict__ f2b,
                 const float* __restrict__ f3w, const float* __restrict__ f3b,
                 const float* __restrict__ f4w, const float* __restrict__ f4b,
                 const float* __restrict__ f5w, const float* __restrict__ f5b,
                 const float* __restrict__ ffw, const float* __restrict__ ffb,
                 float* __restrict__ out, int n)
{
    extern __shared__ float sm[];
    float* sd  = sm;
    float* sx  = sm + 128;
    float* sgv = sm + 256;
    float* sV  = sm + 384;
    float* sgf = sm + 448;
    float* u   = sm + 512;
    float* sz1 = u;
    float* sz2 = u + 64 * ZS;
    float* sz3 = u + 128 * ZS;
    float* sW  = u + 192 * ZS;
    float* shA = u;
    float* shB = u + 64 * HS;
    float* sWf = u + 128 * HS;

    const int t    = threadIdx.x;
    const int base = blockIdx.x * P;
    const int ty   = t >> 4;   // 0..15  -> point groups (p = ty + 16*pi)
    const int tx   = t & 15;   // 0..15  -> output groups (j = tx + 16*ji)

    // ---- load points ----
    for (int i = t; i < P * 2; i += T) {
        int p = i >> 1, c = i & 1;
        int gi = base + p; if (gi >= n) gi = n - 1;
        float xv = X[gi * 2 + c];
        float xs = Xs[gi * 2 + c];
        sx[i] = xv;
        sd[i] = xv - xs;
    }
    __syncthreads();

    // ---- V forward: z1 ----
    for (int i = t; i < P * 64; i += T) {
        int p = i >> 6, j = i & 63;
        float a = sd[p * 2] * Vl1[j * 2] + sd[p * 2 + 1] * Vl1[j * 2 + 1];
        sz1[p * ZS + j] = sr(a);
    }
    // stage V2z  (sW[j][k] row-major)
    for (int i = t; i < 64 * 64; i += T) sW[(i >> 6) * ZS + (i & 63)] = V2z[i];
    __syncthreads();

    // ---- z2 = sr(d@V2x^T + z1@V2z^T) ----
    {
        float acc[4][4];
        #pragma unroll
        for (int pi = 0; pi < 4; pi++) {
            int p = ty + 16 * pi;
            #pragma unroll
            for (int ji = 0; ji < 4; ji++) {
                int j = tx + 16 * ji;
                acc[pi][ji] = sd[p * 2] * V2x[j * 2] + sd[p * 2 + 1] * V2x[j * 2 + 1];
            }
        }
        #pragma unroll 4
        for (int k = 0; k < 64; k++) {
            float a[4], w[4];
            #pragma unroll
            for (int pi = 0; pi < 4; pi++) a[pi] = sz1[(ty + 16 * pi) * ZS + k];
            #pragma unroll
            for (int ji = 0; ji < 4; ji++) w[ji] = sW[(tx + 16 * ji) * ZS + k];
            #pragma unroll
            for (int pi = 0; pi < 4; pi++)
                #pragma unroll
                for (int ji = 0; ji < 4; ji++) acc[pi][ji] += a[pi] * w[ji];
        }
        #pragma unroll
        for (int pi = 0; pi < 4; pi++)
            #pragma unroll
            for (int ji = 0; ji < 4; ji++)
                sz2[(ty + 16 * pi) * ZS + tx + 16 * ji] = sr(acc[pi][ji]);
    }
    __syncthreads();
    // stage V3z
    for (int i = t; i < 64 * 64; i += T) sW[(i >> 6) * ZS + (i & 63)] = V3z[i];
    __syncthreads();

    // ---- z3 = sr(d@V3x^T + z2@V3z^T) ----
    {
        float acc[4][4];
        #pragma unroll
        for (int pi = 0; pi < 4; pi++) {
            int p = ty + 16 * pi;
            #pragma unroll
            for (int ji = 0; ji < 4; ji++) {
                int j = tx + 16 * ji;
                acc[pi][ji] = sd[p * 2] * V3x[j * 2] + sd[p * 2 + 1] * V3x[j * 2 + 1];
            }
        }
        #pragma unroll 4
        for (int k = 0; k < 64; k++) {
            float a[4], w[4];
            #pragma unroll
            for (int pi = 0; pi < 4; pi++) a[pi] = sz2[(ty + 16 * pi) * ZS + k];
            #pragma unroll
            for (int ji = 0; ji < 4; ji++) w[ji] = sW[(tx + 16 * ji) * ZS + k];
            #pragma unroll
            for (int pi = 0; pi < 4; pi++)
                #pragma unroll
                for (int ji = 0; ji < 4; ji++) acc[pi][ji] += a[pi] * w[ji];
        }
        #pragma unroll
        for (int pi = 0; pi < 4; pi++)
            #pragma unroll
            for (int ji = 0; ji < 4; ji++)
                sz3[(ty + 16 * pi) * ZS + tx + 16 * ji] = sr(acc[pi][ji]);
    }
    __syncthreads();   // sW (V3z) is kept for the backward pass

    // ---- zf, V, gf ----
    if (t < 64) {
        int p = t;
        float af = sd[p * 2] * Vfx[0] + sd[p * 2 + 1] * Vfx[1];
        #pragma unroll 4
        for (int k = 0; k < 64; k++) af += Vfz[k] * sz3[p * ZS + k];
        float zf = sr(af);
        sgf[p] = srp(zf) * srp(af);                       // dV/d(af)
        sV[p]  = sr(zf) + TOLC * (sd[p * 2] * sd[p * 2] + sd[p * 2 + 1] * sd[p * 2 + 1]);
    }
    __syncthreads();

    // ---- g_a3 = gf * Vfz * sr'(a3)  (in place over sz3) ----
    for (int i = t; i < P * 64; i += T) {
        int p = i >> 6, j = i & 63;
        float z = sz3[p * ZS + j];
        sz3[p * ZS + j] = sgf[p] * Vfz[j] * srp_out(z);
    }
    __syncthreads();

    // ---- g_a2 = (V3z^T @ g_a3) * sr'(a2)  (in place over sz2; sW holds V3z) ----
    {
        float acc[4][4] = {};
        #pragma unroll 4
        for (int k = 0; k < 64; k++) {
            float a[4], w[4];
            #pragma unroll
            for (int pi = 0; pi < 4; pi++) a[pi] = sz3[(ty + 16 * pi) * ZS + k];
            #pragma unroll
            for (int ji = 0; ji < 4; ji++) w[ji] = sW[k * ZS + tx + 16 * ji];
            #pragma unroll
            for (int pi = 0; pi < 4; pi++)
                #pragma unroll
                for (int ji = 0; ji < 4; ji++) acc[pi][ji] += a[pi] * w[ji];
        }
        #pragma unroll
        for (int pi = 0; pi < 4; pi++)
            #pragma unroll
            for (int ji = 0; ji < 4; ji++) {
                int p = ty + 16 * pi, j = tx + 16 * ji;
                float z = sz2[p * ZS + j];                // own element only -> no race
                sz2[p * ZS + j] = acc[pi][ji] * srp_out(z);
            }
    }
    __syncthreads();
    // restage V2z
    for (int i = t; i < 64 * 64; i += T) sW[(i >> 6) * ZS + (i & 63)] = V2z[i];
    __syncthreads();

    // ---- g_a1 = (V2z^T @ g_a2) * sr'(a1)  (in place over sz1) ----
    {
        float acc[4][4] = {};
        #pragma unroll 4
        for (int k = 0; k < 64; k++) {
            float a[4], w[4];
            #pragma unroll
            for (int pi = 0; pi < 4; pi++) a[pi] = sz2[(ty + 16 * pi) * ZS + k];
            #pragma unroll
            for (int ji = 0; ji < 4; ji++) w[ji] = sW[k * ZS + tx + 16 * ji];
            #pragma unroll
            for (int pi = 0; pi < 4; pi++)
                #pragma unroll
                for (int ji = 0; ji < 4; ji++) acc[pi][ji] += a[pi] * w[ji];
        }
        #pragma unroll
        for (int pi = 0; pi < 4; pi++)
            #pragma unroll
            for (int ji = 0; ji < 4; ji++) {
                int p = ty + 16 * pi, j = tx + 16 * ji;
                float z = sz1[p * ZS + j];
                sz1[p * ZS + j] = acc[pi][ji] * srp_out(z);
            }
    }
    __syncthreads();

    // ---- gradV[p][c] ----
    if (t < 128) {
        int p = t >> 1, c = t & 1;
        float acc = sgf[p] * Vfx[c] + 2.f * TOLC * sd[p * 2 + c];
        #pragma unroll 4
        for (int k = 0; k < 64; k++) {
            acc += sz3[p * ZS + k] * V3x[k * 2 + c];
            acc += sz2[p * ZS + k] * V2x[k * 2 + c];
            acc += sz1[p * ZS + k] * Vl1[k * 2 + c];
        }
        sgv[p * 2 + c] = acc;
    }
    __syncthreads();

    // ================= f_hat =================
    // layer 1
    for (int i = t; i < P * 128; i += T) {
        int p = i >> 7, j = i & 127;
        float a = sx[p * 2] * f1w[j * 2] + sx[p * 2 + 1] * f1w[j * 2 + 1] + f1b[j];
        shA[p * HS + j] = lrelu(a);
    }
    __syncthreads();

    const float* Ws[4] = { f2w, f3w, f4w, f5w };
    const float* Bs[4] = { f2b, f3b, f4b, f5b };
    float* hin = shA;
    float* hout = shB;

    for (int L = 0; L < 4; L++) {
        const float* Wg = Ws[L];
        const float* Bg = Bs[L];
        for (int c0 = 0; c0 < 128; c0 += 64) {
            // stage 64 output rows of W
            for (int i = t; i < 64 * 128; i += T)
                sWf[(i >> 7) * HS + (i & 127)] = Wg[(c0 + (i >> 7)) * 128 + (i & 127)];
            __syncthreads();

            float acc[4][4];
            #pragma unroll
            for (int pi = 0; pi < 4; pi++)
                #pragma unroll
                for (int ji = 0; ji < 4; ji++)
                    acc[pi][ji] = Bg[c0 + tx + 16 * ji];

            #pragma unroll 4
            for (int k = 0; k < 128; k++) {
                float a[4], w[4];
                #pragma unroll
                for (int pi = 0; pi < 4; pi++) a[pi] = hin[(ty + 16 * pi) * HS + k];
                #pragma unroll
                for (int ji = 0; ji < 4; ji++) w[ji] = sWf[(tx + 16 * ji) * HS + k];
                #pragma unroll
                for (int pi = 0; pi < 4; pi++)
                    #pragma unroll
                    for (int ji = 0; ji < 4; ji++) acc[pi][ji] += a[pi] * w[ji];
            }
            #pragma unroll
            for (int pi = 0; pi < 4; pi++)
                #pragma unroll
                for (int ji = 0; ji < 4; ji++)
                    hout[(ty + 16 * pi) * HS + c0 + tx + 16 * ji] = lrelu(acc[pi][ji]);
            __syncthreads();
        }
        float* tmp = hin; hin = hout; hout = tmp;
    }
    // after 4 swaps: final activations are in hin (== shA)

    // ---- final layer + projection ----
    if (t < 64) {
        int p = t;
        float fh0 = ffb[0], fh1 = ffb[1];
        #pragma unroll 4
        for (int k = 0; k < 128; k++) {
            float h = hin[p * HS + k];
            fh0 += h * ffw[k];
            fh1 += h * ffw[128 + k];
        }
        float g0 = sgv[p * 2], g1 = sgv[p * 2 + 1];
        float vn  = g0 * g0 + g1 * g1;
        float fhv = fh0 * g0 + fh1 * g1;
        float num = fhv + ALPHAC * sV[p];
        float fm  = (num > 0.f ? num : 0.f) / (vn + EPSC);
        int gi = base + p;
        if (gi < n) {
            out[gi * 2]     = fh0 - g0 * fm;
            out[gi * 2 + 1] = fh1 - g1 * fm;
        }
    }
}

extern "C" void kernel_launch(void* const* d_in, const int* in_sizes, int n_in,
                              void* d_out, int out_size)
{
    const float* X   = (const float*)d_in[0];
    const float* Xs  = (const float*)d_in[1];
    const float* Vl1 = (const float*)d_in[2];
    const float* V2x = (const float*)d_in[3];
    const float* V2z = (const float*)d_in[4];
    const float* V3x = (const float*)d_in[5];
    const float* V3z = (const float*)d_in[6];
    const float* Vfx = (const float*)d_in[7];
    const float* Vfz = (const float*)d_in[8];
    const float* f1w = (const float*)d_in[9];
    const float* f1b = (const float*)d_in[10];
    const float* f2w = (const float*)d_in[11];
    const float* f2b = (const float*)d_in[12];
    const float* f3w = (const float*)d_in[13];
    const float* f3b = (const float*)d_in[14];
    const float* f4w = (const float*)d_in[15];
    const float* f4b = (const float*)d_in[16];
    const float* f5w = (const float*)d_in[17];
    const float* f5b = (const float*)d_in[18];
    const float* ffw = (const float*)d_in[19];
    const float* ffb = (const float*)d_in[20];

    int n = in_sizes[0] / 2;
    int grid = (n + P - 1) / P;

    cudaFuncSetAttribute(icnn_kernel, cudaFuncAttributeMaxDynamicSharedMemorySize, SMEM_BYTES);

    icnn_kernel<<<grid, T, SMEM_BYTES>>>(
        X, Xs, Vl1, V2x, V2z, V3x, V3z, Vfx, Vfz,
        f1w, f1b, f2w, f2b, f3w, f3b, f4w, f4b, f5w, f5b, ffw, ffb,
        (float*)d_out, n);
}

// round 5
// speedup vs baseline: 2.0132x; 2.0122x over previous
#include <cuda_runtime.h>
#include <cuda_bf16.h>
#include <math.h>
#include <stdint.h>

#define TOLC   0.01f
#define ALPHAC 0.1f
#define SLOPEC 0.01f
#define EPSC   1e-10f

#define NMAX 500096
__device__ float g_gradV[2 * NMAX];
__device__ float g_V[NMAX];

__device__ __forceinline__ float sr(float x)  { return x < 0.f ? 0.f : (x < 1.f ? 0.5f * x * x : x - 0.5f); }
__device__ __forceinline__ float srp(float x) { return x < 0.f ? 0.f : (x < 1.f ? x : 1.f); }
__device__ __forceinline__ float srp_out(float z) { return z <= 0.f ? 0.f : (z < 0.5f ? sqrtf(2.f * z) : 1.f); }
__device__ __forceinline__ float lrelu(float x) { return x >= 0.f ? x : SLOPEC * x; }

// pack two f32 into bf16x2 (v0 in low half)
__device__ __forceinline__ uint32_t packbf(float v0, float v1) {
    uint32_t r; asm("cvt.rn.bf16x2.f32 %0, %1, %2;" : "=r"(r) : "f"(v1), "f"(v0)); return r;
}
__device__ __forceinline__ float bf16rt(float v) {     // round-trip through bf16
    return __bfloat162float(__float2bfloat16(v));
}

__device__ __forceinline__ void mma_bf16(float* c,
                                         uint32_t a0, uint32_t a1, uint32_t a2, uint32_t a3,
                                         uint32_t b0, uint32_t b1) {
    asm volatile("mma.sync.aligned.m16n8k16.row.col.f32.bf16.bf16.f32 "
                 "{%0,%1,%2,%3}, {%4,%5,%6,%7}, {%8,%9}, {%0,%1,%2,%3};"
                 : "+f"(c[0]), "+f"(c[1]), "+f"(c[2]), "+f"(c[3])
                 : "r"(a0), "r"(a1), "r"(a2), "r"(a3), "r"(b0), "r"(b1));
}

// ============================================================================
// Kernel A: ICNN V network forward + manual VJP (SIMT fp32, proven)
// ============================================================================
constexpr int PA = 64;
constexpr int TA = 256;
constexpr int ZS = 65;
constexpr int SMEMA_BYTES = (256 + 4 * 64 * ZS) * 4;   // 67584

__global__ __launch_bounds__(TA, 3)
void vnet_kernel(const float* __restrict__ X,   const float* __restrict__ Xs,
                 const float* __restrict__ Vl1, const float* __restrict__ V2x,
                 const float* __restrict__ V2z, const float* __restrict__ V3x,
                 const float* __restrict__ V3z, const float* __restrict__ Vfx,
                 const float* __restrict__ Vfz, int n)
{
    extern __shared__ float sm[];
    float* sd  = sm;
    float* sV  = sm + 128;
    float* sgf = sm + 192;
    float* u   = sm + 256;
    float* sz1 = u;
    float* sz2 = u + 64 * ZS;
    float* sz3 = u + 128 * ZS;
    float* sW  = u + 192 * ZS;

    const int t    = threadIdx.x;
    const int base = blockIdx.x * PA;
    const int ty   = t >> 4;
    const int tx   = t & 15;

    for (int i = t; i < PA * 2; i += TA) {
        int p = i >> 1, c = i & 1;
        int gi = base + p; if (gi >= n) gi = n - 1;
        sd[i] = X[gi * 2 + c] - Xs[gi * 2 + c];
    }
    __syncthreads();

    for (int i = t; i < PA * 64; i += TA) {
        int p = i >> 6, j = i & 63;
        float a = sd[p * 2] * Vl1[j * 2] + sd[p * 2 + 1] * Vl1[j * 2 + 1];
        sz1[p * ZS + j] = sr(a);
    }
    for (int i = t; i < 64 * 64; i += TA) sW[(i >> 6) * ZS + (i & 63)] = V2z[i];
    __syncthreads();

    {   // z2
        float acc[4][4];
        #pragma unroll
        for (int pi = 0; pi < 4; pi++) {
            int p = ty + 16 * pi;
            #pragma unroll
            for (int ji = 0; ji < 4; ji++) {
                int j = tx + 16 * ji;
                acc[pi][ji] = sd[p * 2] * V2x[j * 2] + sd[p * 2 + 1] * V2x[j * 2 + 1];
            }
        }
        #pragma unroll 4
        for (int k = 0; k < 64; k++) {
            float a[4], w[4];
            #pragma unroll
            for (int pi = 0; pi < 4; pi++) a[pi] = sz1[(ty + 16 * pi) * ZS + k];
            #pragma unroll
            for (int ji = 0; ji < 4; ji++) w[ji] = sW[(tx + 16 * ji) * ZS + k];
            #pragma unroll
            for (int pi = 0; pi < 4; pi++)
                #pragma unroll
                for (int ji = 0; ji < 4; ji++) acc[pi][ji] += a[pi] * w[ji];
        }
        #pragma unroll
        for (int pi = 0; pi < 4; pi++)
            #pragma unroll
            for (int ji = 0; ji < 4; ji++)
                sz2[(ty + 16 * pi) * ZS + tx + 16 * ji] = sr(acc[pi][ji]);
    }
    __syncthreads();
    for (int i = t; i < 64 * 64; i += TA) sW[(i >> 6) * ZS + (i & 63)] = V3z[i];
    __syncthreads();

    {   // z3
        float acc[4][4];
        #pragma unroll
        for (int pi = 0; pi < 4; pi++) {
            int p = ty + 16 * pi;
            #pragma unroll
            for (int ji = 0; ji < 4; ji++) {
                int j = tx + 16 * ji;
                acc[pi][ji] = sd[p * 2] * V3x[j * 2] + sd[p * 2 + 1] * V3x[j * 2 + 1];
            }
        }
        #pragma unroll 4
        for (int k = 0; k < 64; k++) {
            float a[4], w[4];
            #pragma unroll
            for (int pi = 0; pi < 4; pi++) a[pi] = sz2[(ty + 16 * pi) * ZS + k];
            #pragma unroll
            for (int ji = 0; ji < 4; ji++) w[ji] = sW[(tx + 16 * ji) * ZS + k];
            #pragma unroll
            for (int pi = 0; pi < 4; pi++)
                #pragma unroll
                for (int ji = 0; ji < 4; ji++) acc[pi][ji] += a[pi] * w[ji];
        }
        #pragma unroll
        for (int pi = 0; pi < 4; pi++)
            #pragma unroll
            for (int ji = 0; ji < 4; ji++)
                sz3[(ty + 16 * pi) * ZS + tx + 16 * ji] = sr(acc[pi][ji]);
    }
    __syncthreads();

    if (t < 64) {
        int p = t;
        float af = sd[p * 2] * Vfx[0] + sd[p * 2 + 1] * Vfx[1];
        #pragma unroll 4
        for (int k = 0; k < 64; k++) af += Vfz[k] * sz3[p * ZS + k];
        float zf = sr(af);
        sgf[p] = srp(zf) * srp(af);
        sV[p]  = sr(zf) + TOLC * (sd[p * 2] * sd[p * 2] + sd[p * 2 + 1] * sd[p * 2 + 1]);
    }
    __syncthreads();

    for (int i = t; i < PA * 64; i += TA) {
        int p = i >> 6, j = i & 63;
        float z = sz3[p * ZS + j];
        sz3[p * ZS + j] = sgf[p] * Vfz[j] * srp_out(z);
    }
    __syncthreads();

    {   // g_a2 (sW holds V3z)
        float acc[4][4] = {};
        #pragma unroll 4
        for (int k = 0; k < 64; k++) {
            float a[4], w[4];
            #pragma unroll
            for (int pi = 0; pi < 4; pi++) a[pi] = sz3[(ty + 16 * pi) * ZS + k];
            #pragma unroll
            for (int ji = 0; ji < 4; ji++) w[ji] = sW[k * ZS + tx + 16 * ji];
            #pragma unroll
            for (int pi = 0; pi < 4; pi++)
                #pragma unroll
                for (int ji = 0; ji < 4; ji++) acc[pi][ji] += a[pi] * w[ji];
        }
        #pragma unroll
        for (int pi = 0; pi < 4; pi++)
            #pragma unroll
            for (int ji = 0; ji < 4; ji++) {
                int p = ty + 16 * pi, j = tx + 16 * ji;
                float z = sz2[p * ZS + j];
                sz2[p * ZS + j] = acc[pi][ji] * srp_out(z);
            }
    }
    __syncthreads();
    for (int i = t; i < 64 * 64; i += TA) sW[(i >> 6) * ZS + (i & 63)] = V2z[i];
    __syncthreads();

    {   // g_a1
        float acc[4][4] = {};
        #pragma unroll 4
        for (int k = 0; k < 64; k++) {
            float a[4], w[4];
            #pragma unroll
            for (int pi = 0; pi < 4; pi++) a[pi] = sz2[(ty + 16 * pi) * ZS + k];
            #pragma unroll
            for (int ji = 0; ji < 4; ji++) w[ji] = sW[k * ZS + tx + 16 * ji];
            #pragma unroll
            for (int pi = 0; pi < 4; pi++)
                #pragma unroll
                for (int ji = 0; ji < 4; ji++) acc[pi][ji] += a[pi] * w[ji];
        }
        #pragma unroll
        for (int pi = 0; pi < 4; pi++)
            #pragma unroll
            for (int ji = 0; ji < 4; ji++) {
                int p = ty + 16 * pi, j = tx + 16 * ji;
                float z = sz1[p * ZS + j];
                sz1[p * ZS + j] = acc[pi][ji] * srp_out(z);
            }
    }
    __syncthreads();

    if (t < 128) {
        int p = t >> 1, c = t & 1;
        float acc = sgf[p] * Vfx[c] + 2.f * TOLC * sd[p * 2 + c];
        #pragma unroll 4
        for (int k = 0; k < 64; k++) {
            acc += sz3[p * ZS + k] * V3x[k * 2 + c];
            acc += sz2[p * ZS + k] * V2x[k * 2 + c];
            acc += sz1[p * ZS + k] * Vl1[k * 2 + c];
        }
        int gi = base + p;
        if (gi < n) g_gradV[gi * 2 + c] = acc;
    }
    if (t < 64) {
        int gi = base + t;
        if (gi < n) g_V[gi] = sV[t];
    }
}

// ============================================================================
// Kernel B: f_hat MLP via mma.sync bf16 (2x-bf16 split) + projection
// ============================================================================
constexpr int TB = 256;
constexpr int ST = 136;                        // bf16 row stride (272 B: conflict-free)
constexpr int TILE_B = 128 * ST * 2;           // 34816 bytes per bf16 tile
constexpr int B_AHI  = 0;
constexpr int B_ALO  = TILE_B;
constexpr int B_WHI  = 2 * TILE_B;
constexpr int B_WLO  = 3 * TILE_B;
constexpr int B_MISC = 4 * TILE_B;             // 139264
// misc floats: sx[256], sb[128], sff[258], sp0[128], sp1[128]
constexpr int SMEMB_BYTES = B_MISC + 4 * (256 + 128 + 258 + 128 + 128);

__global__ __launch_bounds__(TB, 1)
void fhat_kernel(const float* __restrict__ X,
                 const float* __restrict__ f1w, const float* __restrict__ f1b,
                 const float* __restrict__ f2w, const float* __restrict__ f2b,
                 const float* __restrict__ f3w, const float* __restrict__ f3b,
                 const float* __restrict__ f4w, const float* __restrict__ f4b,
                 const float* __restrict__ f5w, const float* __restrict__ f5b,
                 const float* __restrict__ ffw, const float* __restrict__ ffb,
                 float* __restrict__ out, int n)
{
    extern __shared__ __align__(16) char smb[];
    __nv_bfloat16* Ahi = (__nv_bfloat16*)(smb + B_AHI);
    __nv_bfloat16* Alo = (__nv_bfloat16*)(smb + B_ALO);
    __nv_bfloat16* Whi = (__nv_bfloat16*)(smb + B_WHI);
    __nv_bfloat16* Wlo = (__nv_bfloat16*)(smb + B_WLO);
    float* mf  = (float*)(smb + B_MISC);
    float* sx  = mf;            // 256
    float* sb  = mf + 256;      // 128
    float* sff = mf + 384;      // 258
    float* sp0 = mf + 642;      // 128
    float* sp1 = mf + 770;      // 128

    const int t    = threadIdx.x;
    const int wid  = t >> 5;
    const int lane = t & 31;
    const int gid  = lane >> 2;      // 0..7
    const int tig  = lane & 3;       // 0..3
    const int r0   = wid * 16;       // warp's M slab
    const int base = blockIdx.x * 128;

    {   // stage X (clamped)
        int p = t >> 1, c = t & 1;
        int gi = base + p; if (gi >= n) gi = n - 1;
        sx[t] = X[gi * 2 + c];
    }
    for (int i = t; i < 258; i += TB) sff[i] = (i < 256) ? ffw[i] : ffb[i - 256];
    __syncthreads();

    // ---- layer 1 (K=2, SIMT) -> A hi/lo ----
    for (int i = t; i < 128 * 128; i += TB) {
        int p = i >> 7, j = i & 127;
        float v  = lrelu(sx[2 * p] * f1w[2 * j] + sx[2 * p + 1] * f1w[2 * j + 1] + f1b[j]);
        float h  = bf16rt(v);
        Ahi[p * ST + j] = __float2bfloat16(v);
        Alo[p * ST + j] = __float2bfloat16(v - h);
    }
    __syncthreads();

    const float* Ws[4] = { f2w, f3w, f4w, f5w };
    const float* Bs[4] = { f2b, f3b, f4b, f5b };

    for (int L = 0; L < 4; L++) {
        // ---- stage W (128x128) as bf16 hi/lo ----
        {
            const float* Wg = Ws[L];
            for (int i = t; i < 128 * 32; i += TB) {
                int j  = i >> 5;
                int k4 = (i & 31) << 2;
                float4 w = *(const float4*)(Wg + j * 128 + k4);
                float h0 = bf16rt(w.x), h1 = bf16rt(w.y), h2 = bf16rt(w.z), h3 = bf16rt(w.w);
                uint32_t hp0 = packbf(w.x, w.y), hp1 = packbf(w.z, w.w);
                uint32_t lp0 = packbf(w.x - h0, w.y - h1), lp1 = packbf(w.z - h2, w.w - h3);
                *(uint2*)(Whi + j * ST + k4) = make_uint2(hp0, hp1);
                *(uint2*)(Wlo + j * ST + k4) = make_uint2(lp0, lp1);
            }
            if (t < 128) sb[t] = Bs[L][t];
        }
        __syncthreads();

        // ---- GEMM: acc[nt][4] = A(128x128) @ W^T ----
        float acc[16][4];
        #pragma unroll
        for (int nt = 0; nt < 16; nt++)
            #pragma unroll
            for (int q = 0; q < 4; q++) acc[nt][q] = 0.f;

        #pragma unroll
        for (int kt = 0; kt < 8; kt++) {
            const int ka = kt * 16 + 2 * tig;
            uint32_t ah0 = *(const uint32_t*)(Ahi + (r0 + gid) * ST + ka);
            uint32_t ah1 = *(const uint32_t*)(Ahi + (r0 + gid + 8) * ST + ka);
            uint32_t ah2 = *(const uint32_t*)(Ahi + (r0 + gid) * ST + ka + 8);
            uint32_t ah3 = *(const uint32_t*)(Ahi + (r0 + gid + 8) * ST + ka + 8);
            uint32_t al0 = *(const uint32_t*)(Alo + (r0 + gid) * ST + ka);
            uint32_t al1 = *(const uint32_t*)(Alo + (r0 + gid + 8) * ST + ka);
            uint32_t al2 = *(const uint32_t*)(Alo + (r0 + gid) * ST + ka + 8);
            uint32_t al3 = *(const uint32_t*)(Alo + (r0 + gid + 8) * ST + ka + 8);
            #pragma unroll
            for (int nt = 0; nt < 16; nt++) {
                const int nrow = nt * 8 + gid;
                uint32_t bh0 = *(const uint32_t*)(Whi + nrow * ST + ka);
                uint32_t bh1 = *(const uint32_t*)(Whi + nrow * ST + ka + 8);
                uint32_t bl0 = *(const uint32_t*)(Wlo + nrow * ST + ka);
                uint32_t bl1 = *(const uint32_t*)(Wlo + nrow * ST + ka + 8);
                mma_bf16(acc[nt], ah0, ah1, ah2, ah3, bh0, bh1);
                mma_bf16(acc[nt], ah0, ah1, ah2, ah3, bl0, bl1);
                mma_bf16(acc[nt], al0, al1, al2, al3, bh0, bh1);
            }
        }
        __syncthreads();   // everyone done reading A before we overwrite it

        if (L < 3) {
            // ---- epilogue: bias + lrelu + split back to A ----
            #pragma unroll
            for (int nt = 0; nt < 16; nt++) {
                int c = nt * 8 + 2 * tig;
                float v0 = lrelu(acc[nt][0] + sb[c]);
                float v1 = lrelu(acc[nt][1] + sb[c + 1]);
                float v2 = lrelu(acc[nt][2] + sb[c]);
                float v3 = lrelu(acc[nt][3] + sb[c + 1]);
                float h0 = bf16rt(v0), h1 = bf16rt(v1), h2 = bf16rt(v2), h3 = bf16rt(v3);
                *(uint32_t*)(Ahi + (r0 + gid) * ST + c)     = packbf(v0, v1);
                *(uint32_t*)(Ahi + (r0 + gid + 8) * ST + c) = packbf(v2, v3);
                *(uint32_t*)(Alo + (r0 + gid) * ST + c)     = packbf(v0 - h0, v1 - h1);
                *(uint32_t*)(Alo + (r0 + gid + 8) * ST + c) = packbf(v2 - h2, v3 - h3);
            }
            __syncthreads();
        } else {
            // ---- last hidden layer: fold directly into ff dot products ----
            float p0 = 0.f, p1 = 0.f, q0 = 0.f, q1 = 0.f;
            #pragma unroll
            for (int nt = 0; nt < 16; nt++) {
                int c = nt * 8 + 2 * tig;
                float v0 = lrelu(acc[nt][0] + sb[c]);
                float v1 = lrelu(acc[nt][1] + sb[c + 1]);
                float v2 = lrelu(acc[nt][2] + sb[c]);
                float v3 = lrelu(acc[nt][3] + sb[c + 1]);
                p0 = fmaf(v0, sff[c], fmaf(v1, sff[c + 1], p0));
                p1 = fmaf(v0, sff[128 + c], fmaf(v1, sff[129 + c], p1));
                q0 = fmaf(v2, sff[c], fmaf(v3, sff[c + 1], q0));
                q1 = fmaf(v2, sff[128 + c], fmaf(v3, sff[129 + c], q1));
            }
            // reduce over tig (4 lanes within each row group)
            #pragma unroll
            for (int m = 1; m < 4; m <<= 1) {
                p0 += __shfl_xor_sync(0xFFFFFFFFu, p0, m);
                p1 += __shfl_xor_sync(0xFFFFFFFFu, p1, m);
                q0 += __shfl_xor_sync(0xFFFFFFFFu, q0, m);
                q1 += __shfl_xor_sync(0xFFFFFFFFu, q1, m);
            }
            if (tig == 0) {
                sp0[r0 + gid] = p0;  sp1[r0 + gid] = p1;
                sp0[r0 + gid + 8] = q0;  sp1[r0 + gid + 8] = q1;
            }
            __syncthreads();
        }
    }

    // ---- final projection ----
    if (t < 128) {
        int gi = base + t;
        if (gi < n) {
            float fh0 = sff[256] + sp0[t];
            float fh1 = sff[257] + sp1[t];
            float g0 = g_gradV[2 * gi], g1 = g_gradV[2 * gi + 1];
            float V  = g_V[gi];
            float vn  = g0 * g0 + g1 * g1;
            float num = fh0 * g0 + fh1 * g1 + ALPHAC * V;
            float fm  = (num > 0.f ? num : 0.f) / (vn + EPSC);
            out[2 * gi]     = fh0 - g0 * fm;
            out[2 * gi + 1] = fh1 - g1 * fm;
        }
    }
}

// ============================================================================
extern "C" void kernel_launch(void* const* d_in, const int* in_sizes, int n_in,
                              void* d_out, int out_size)
{
    const float* X   = (const float*)d_in[0];
    const float* Xs  = (const float*)d_in[1];
    const float* Vl1 = (const float*)d_in[2];
    const float* V2x = (const float*)d_in[3];
    const float* V2z = (const float*)d_in[4];
    const float* V3x = (const float*)d_in[5];
    const float* V3z = (const float*)d_in[6];
    const float* Vfx = (const float*)d_in[7];
    const float* Vfz = (const float*)d_in[8];
    const float* f1w = (const float*)d_in[9];
    const float* f1b = (const float*)d_in[10];
    const float* f2w = (const float*)d_in[11];
    const float* f2b = (const float*)d_in[12];
    const float* f3w = (const float*)d_in[13];
    const float* f3b = (const float*)d_in[14];
    const float* f4w = (const float*)d_in[15];
    const float* f4b = (const float*)d_in[16];
    const float* f5w = (const float*)d_in[17];
    const float* f5b = (const float*)d_in[18];
    const float* ffw = (const float*)d_in[19];
    const float* ffb = (const float*)d_in[20];

    int n = in_sizes[0] / 2;

    cudaFuncSetAttribute(vnet_kernel, cudaFuncAttributeMaxDynamicSharedMemorySize, SMEMA_BYTES);
    cudaFuncSetAttribute(fhat_kernel, cudaFuncAttributeMaxDynamicSharedMemorySize, SMEMB_BYTES);

    vnet_kernel<<<(n + PA - 1) / PA, TA, SMEMA_BYTES>>>(
        X, Xs, Vl1, V2x, V2z, V3x, V3z, Vfx, Vfz, n);

    fhat_kernel<<<(n + 127) / 128, TB, SMEMB_BYTES>>>(
        X, f1w, f1b, f2w, f2b, f3w, f3b, f4w, f4b, f5w, f5b, ffw, ffb,
        (float*)d_out, n);
}

// round 6
// speedup vs baseline: 2.2259x; 1.1056x over previous
#include <cuda_runtime.h>
#include <cuda_bf16.h>
#include <math.h>
#include <stdint.h>

#define TOLC   0.01f
#define ALPHAC 0.1f
#define SLOPEC 0.01f
#define EPSC   1e-10f

#define NMAX 500096
__device__ float g_gradV[2 * NMAX];
__device__ float g_V[NMAX];

__device__ __forceinline__ float sr(float x)  { return x < 0.f ? 0.f : (x < 1.f ? 0.5f * x * x : x - 0.5f); }
__device__ __forceinline__ float srp(float x) { return x < 0.f ? 0.f : (x < 1.f ? x : 1.f); }
__device__ __forceinline__ float srp_out(float z) { return z <= 0.f ? 0.f : (z < 0.5f ? sqrtf(2.f * z) : 1.f); }
__device__ __forceinline__ float lrelu(float x) { return x >= 0.f ? x : SLOPEC * x; }

__device__ __forceinline__ uint32_t packbf(float v0, float v1) {
    uint32_t r; asm("cvt.rn.bf16x2.f32 %0, %1, %2;" : "=r"(r) : "f"(v1), "f"(v0)); return r;
}
__device__ __forceinline__ float bf16rt(float v) {
    return __bfloat162float(__float2bfloat16(v));
}
__device__ __forceinline__ uint32_t smem_u32(const void* p) {
    uint32_t a;
    asm("{ .reg .u64 t; cvta.to.shared.u64 t, %1; cvt.u32.u64 %0, t; }" : "=r"(a) : "l"(p));
    return a;
}
__device__ __forceinline__ void ldsm4(uint32_t* r, uint32_t addr) {
    asm volatile("ldmatrix.sync.aligned.m8n8.x4.shared.b16 {%0,%1,%2,%3}, [%4];"
                 : "=r"(r[0]), "=r"(r[1]), "=r"(r[2]), "=r"(r[3]) : "r"(addr));
}
__device__ __forceinline__ void mma_bf16(float* c,
                                         uint32_t a0, uint32_t a1, uint32_t a2, uint32_t a3,
                                         uint32_t b0, uint32_t b1) {
    asm volatile("mma.sync.aligned.m16n8k16.row.col.f32.bf16.bf16.f32 "
                 "{%0,%1,%2,%3}, {%4,%5,%6,%7}, {%8,%9}, {%0,%1,%2,%3};"
                 : "+f"(c[0]), "+f"(c[1]), "+f"(c[2]), "+f"(c[3])
                 : "r"(a0), "r"(a1), "r"(a2), "r"(a3), "r"(b0), "r"(b1));
}

// ============================================================================
// Kernel A: ICNN V network forward + manual VJP (SIMT fp32, proven)
// ============================================================================
constexpr int PA = 64;
constexpr int TA = 256;
constexpr int ZS = 65;
constexpr int SMEMA_BYTES = (256 + 4 * 64 * ZS) * 4;   // 67584

__global__ __launch_bounds__(TA, 3)
void vnet_kernel(const float* __restrict__ X,   const float* __restrict__ Xs,
                 const float* __restrict__ Vl1, const float* __restrict__ V2x,
                 const float* __restrict__ V2z, const float* __restrict__ V3x,
                 const float* __restrict__ V3z, const float* __restrict__ Vfx,
                 const float* __restrict__ Vfz, int n)
{
    extern __shared__ float sm[];
    float* sd  = sm;
    float* sV  = sm + 128;
    float* sgf = sm + 192;
    float* u   = sm + 256;
    float* sz1 = u;
    float* sz2 = u + 64 * ZS;
    float* sz3 = u + 128 * ZS;
    float* sW  = u + 192 * ZS;

    const int t    = threadIdx.x;
    const int base = blockIdx.x * PA;
    const int ty   = t >> 4;
    const int tx   = t & 15;

    for (int i = t; i < PA * 2; i += TA) {
        int p = i >> 1, c = i & 1;
        int gi = base + p; if (gi >= n) gi = n - 1;
        sd[i] = X[gi * 2 + c] - Xs[gi * 2 + c];
    }
    __syncthreads();

    for (int i = t; i < PA * 64; i += TA) {
        int p = i >> 6, j = i & 63;
        float a = sd[p * 2] * Vl1[j * 2] + sd[p * 2 + 1] * Vl1[j * 2 + 1];
        sz1[p * ZS + j] = sr(a);
    }
    for (int i = t; i < 64 * 64; i += TA) sW[(i >> 6) * ZS + (i & 63)] = V2z[i];
    __syncthreads();

    {   // z2
        float acc[4][4];
        #pragma unroll
        for (int pi = 0; pi < 4; pi++) {
            int p = ty + 16 * pi;
            #pragma unroll
            for (int ji = 0; ji < 4; ji++) {
                int j = tx + 16 * ji;
                acc[pi][ji] = sd[p * 2] * V2x[j * 2] + sd[p * 2 + 1] * V2x[j * 2 + 1];
            }
        }
        #pragma unroll 4
        for (int k = 0; k < 64; k++) {
            float a[4], w[4];
            #pragma unroll
            for (int pi = 0; pi < 4; pi++) a[pi] = sz1[(ty + 16 * pi) * ZS + k];
            #pragma unroll
            for (int ji = 0; ji < 4; ji++) w[ji] = sW[(tx + 16 * ji) * ZS + k];
            #pragma unroll
            for (int pi = 0; pi < 4; pi++)
                #pragma unroll
                for (int ji = 0; ji < 4; ji++) acc[pi][ji] += a[pi] * w[ji];
        }
        #pragma unroll
        for (int pi = 0; pi < 4; pi++)
            #pragma unroll
            for (int ji = 0; ji < 4; ji++)
                sz2[(ty + 16 * pi) * ZS + tx + 16 * ji] = sr(acc[pi][ji]);
    }
    __syncthreads();
    for (int i = t; i < 64 * 64; i += TA) sW[(i >> 6) * ZS + (i & 63)] = V3z[i];
    __syncthreads();

    {   // z3
        float acc[4][4];
        #pragma unroll
        for (int pi = 0; pi < 4; pi++) {
            int p = ty + 16 * pi;
            #pragma unroll
            for (int ji = 0; ji < 4; ji++) {
                int j = tx + 16 * ji;
                acc[pi][ji] = sd[p * 2] * V3x[j * 2] + sd[p * 2 + 1] * V3x[j * 2 + 1];
            }
        }
        #pragma unroll 4
        for (int k = 0; k < 64; k++) {
            float a[4], w[4];
            #pragma unroll
            for (int pi = 0; pi < 4; pi++) a[pi] = sz2[(ty + 16 * pi) * ZS + k];
            #pragma unroll
            for (int ji = 0; ji < 4; ji++) w[ji] = sW[(tx + 16 * ji) * ZS + k];
            #pragma unroll
            for (int pi = 0; pi < 4; pi++)
                #pragma unroll
                for (int ji = 0; ji < 4; ji++) acc[pi][ji] += a[pi] * w[ji];
        }
        #pragma unroll
        for (int pi = 0; pi < 4; pi++)
            #pragma unroll
            for (int ji = 0; ji < 4; ji++)
                sz3[(ty + 16 * pi) * ZS + tx + 16 * ji] = sr(acc[pi][ji]);
    }
    __syncthreads();

    if (t < 64) {
        int p = t;
        float af = sd[p * 2] * Vfx[0] + sd[p * 2 + 1] * Vfx[1];
        #pragma unroll 4
        for (int k = 0; k < 64; k++) af += Vfz[k] * sz3[p * ZS + k];
        float zf = sr(af);
        sgf[p] = srp(zf) * srp(af);
        sV[p]  = sr(zf) + TOLC * (sd[p * 2] * sd[p * 2] + sd[p * 2 + 1] * sd[p * 2 + 1]);
    }
    __syncthreads();

    for (int i = t; i < PA * 64; i += TA) {
        int p = i >> 6, j = i & 63;
        float z = sz3[p * ZS + j];
        sz3[p * ZS + j] = sgf[p] * Vfz[j] * srp_out(z);
    }
    __syncthreads();

    {   // g_a2 (sW holds V3z)
        float acc[4][4] = {};
        #pragma unroll 4
        for (int k = 0; k < 64; k++) {
            float a[4], w[4];
            #pragma unroll
            for (int pi = 0; pi < 4; pi++) a[pi] = sz3[(ty + 16 * pi) * ZS + k];
            #pragma unroll
            for (int ji = 0; ji < 4; ji++) w[ji] = sW[k * ZS + tx + 16 * ji];
            #pragma unroll
            for (int pi = 0; pi < 4; pi++)
                #pragma unroll
                for (int ji = 0; ji < 4; ji++) acc[pi][ji] += a[pi] * w[ji];
        }
        #pragma unroll
        for (int pi = 0; pi < 4; pi++)
            #pragma unroll
            for (int ji = 0; ji < 4; ji++) {
                int p = ty + 16 * pi, j = tx + 16 * ji;
                float z = sz2[p * ZS + j];
                sz2[p * ZS + j] = acc[pi][ji] * srp_out(z);
            }
    }
    __syncthreads();
    for (int i = t; i < 64 * 64; i += TA) sW[(i >> 6) * ZS + (i & 63)] = V2z[i];
    __syncthreads();

    {   // g_a1
        float acc[4][4] = {};
        #pragma unroll 4
        for (int k = 0; k < 64; k++) {
            float a[4], w[4];
            #pragma unroll
            for (int pi = 0; pi < 4; pi++) a[pi] = sz2[(ty + 16 * pi) * ZS + k];
            #pragma unroll
            for (int ji = 0; ji < 4; ji++) w[ji] = sW[k * ZS + tx + 16 * ji];
            #pragma unroll
            for (int pi = 0; pi < 4; pi++)
                #pragma unroll
                for (int ji = 0; ji < 4; ji++) acc[pi][ji] += a[pi] * w[ji];
        }
        #pragma unroll
        for (int pi = 0; pi < 4; pi++)
            #pragma unroll
            for (int ji = 0; ji < 4; ji++) {
                int p = ty + 16 * pi, j = tx + 16 * ji;
                float z = sz1[p * ZS + j];
                sz1[p * ZS + j] = acc[pi][ji] * srp_out(z);
            }
    }
    __syncthreads();

    if (t < 128) {
        int p = t >> 1, c = t & 1;
        float acc = sgf[p] * Vfx[c] + 2.f * TOLC * sd[p * 2 + c];
        #pragma unroll 4
        for (int k = 0; k < 64; k++) {
            acc += sz3[p * ZS + k] * V3x[k * 2 + c];
            acc += sz2[p * ZS + k] * V2x[k * 2 + c];
            acc += sz1[p * ZS + k] * Vl1[k * 2 + c];
        }
        int gi = base + p;
        if (gi < n) g_gradV[gi * 2 + c] = acc;
    }
    if (t < 64) {
        int gi = base + t;
        if (gi < n) g_V[gi] = sV[t];
    }
}

// ============================================================================
// Kernel B: f_hat MLP via mma.sync bf16 (2x-bf16 split), ldmatrix feeds,
//           W staged in N-halves -> 2 CTAs/SM
// ============================================================================
constexpr int TB = 256;
constexpr int ST = 136;                        // bf16 row stride (272 B, conflict-free)
constexpr int TILE_A = 128 * ST * 2;           // 34816 B
constexpr int TILE_W = 64 * ST * 2;            // 17408 B
constexpr int B_AHI  = 0;
constexpr int B_ALO  = TILE_A;
constexpr int B_WHI  = 2 * TILE_A;
constexpr int B_WLO  = 2 * TILE_A + TILE_W;
constexpr int B_MISC = 2 * TILE_A + 2 * TILE_W;   // 104448
// misc floats: sx[256], sb[128], sff[258], sp0[128], sp1[128] = 898
constexpr int SMEMB_BYTES = B_MISC + 4 * 898;     // 108040 < 113664 -> 2 CTAs/SM

__global__ __launch_bounds__(TB, 2)
void fhat_kernel(const float* __restrict__ X,
                 const float* __restrict__ f1w, const float* __restrict__ f1b,
                 const float* __restrict__ f2w, const float* __restrict__ f2b,
                 const float* __restrict__ f3w, const float* __restrict__ f3b,
                 const float* __restrict__ f4w, const float* __restrict__ f4b,
                 const float* __restrict__ f5w, const float* __restrict__ f5b,
                 const float* __restrict__ ffw, const float* __restrict__ ffb,
                 float* __restrict__ out, int n)
{
    extern __shared__ __align__(16) char smb[];
    __nv_bfloat16* Ahi = (__nv_bfloat16*)(smb + B_AHI);
    __nv_bfloat16* Alo = (__nv_bfloat16*)(smb + B_ALO);
    __nv_bfloat16* Whi = (__nv_bfloat16*)(smb + B_WHI);
    __nv_bfloat16* Wlo = (__nv_bfloat16*)(smb + B_WLO);
    float* mf  = (float*)(smb + B_MISC);
    float* sx  = mf;            // 256
    float* sb  = mf + 256;      // 128
    float* sff = mf + 384;      // 258
    float* sp0 = mf + 642;      // 128
    float* sp1 = mf + 770;      // 128

    const int t    = threadIdx.x;
    const int wid  = t >> 5;
    const int lane = t & 31;
    const int gid  = lane >> 2;
    const int tig  = lane & 3;
    const int r0   = wid * 16;
    const int base = blockIdx.x * 128;

    // ldmatrix per-lane base byte offsets
    // A x4: lanes 0-7 rows r..r+7 col 0 | 8-15 rows +8 col 0 | 16-23 col 8 | 24-31 rows+8 col 8
    const int aRow = r0 + (lane & 7) + ((lane >> 3) & 1) * 8;
    const int aCol = ((lane >> 4) & 1) * 8;
    const uint32_t aOff = (uint32_t)(aRow * ST + aCol) * 2;
    // B x4 (pair of 8-col tiles): lanes 0-7 rows 0-7 col 0 (b0 of nt) | 8-15 rows 0-7 col 8 (b1 of nt)
    //                             | 16-23 rows 8-15 col 0 (b0 of nt+1) | 24-31 rows 8-15 col 8 (b1 of nt+1)
    const int bRow = (lane & 7) + ((lane >> 4) & 1) * 8;
    const int bCol = ((lane >> 3) & 1) * 8;
    const uint32_t bOff = (uint32_t)(bRow * ST + bCol) * 2;

    const uint32_t aHiB = smem_u32(Ahi) + aOff;
    const uint32_t aLoB = smem_u32(Alo) + aOff;
    const uint32_t wHiB = smem_u32(Whi) + bOff;
    const uint32_t wLoB = smem_u32(Wlo) + bOff;

    {   // stage X (clamped)
        int p = t >> 1, c = t & 1;
        int gi = base + p; if (gi >= n) gi = n - 1;
        sx[t] = X[gi * 2 + c];
    }
    for (int i = t; i < 258; i += TB) sff[i] = (i < 256) ? ffw[i] : ffb[i - 256];
    __syncthreads();

    // ---- layer 1 (K=2, SIMT) -> A hi/lo ----
    for (int i = t; i < 128 * 128; i += TB) {
        int p = i >> 7, j = i & 127;
        float v  = lrelu(sx[2 * p] * f1w[2 * j] + sx[2 * p + 1] * f1w[2 * j + 1] + f1b[j]);
        float h  = bf16rt(v);
        Ahi[p * ST + j] = __float2bfloat16(v);
        Alo[p * ST + j] = __float2bfloat16(v - h);
    }
    __syncthreads();

    const float* Ws[4] = { f2w, f3w, f4w, f5w };
    const float* Bs[4] = { f2b, f3b, f4b, f5b };

    for (int L = 0; L < 4; L++) {
        const float* Wg = Ws[L];
        float acc[16][4];
        #pragma unroll
        for (int q = 0; q < 16; q++)
            #pragma unroll
            for (int c = 0; c < 4; c++) acc[q][c] = 0.f;

        #pragma unroll 1
        for (int half = 0; half < 2; half++) {
            // stage W half (64 out rows x 128 k) hi/lo
            for (int i = t; i < 64 * 32; i += TB) {
                int j  = i >> 5;
                int k4 = (i & 31) << 2;
                float4 w = *(const float4*)(Wg + (half * 64 + j) * 128 + k4);
                float h0 = bf16rt(w.x), h1 = bf16rt(w.y), h2 = bf16rt(w.z), h3 = bf16rt(w.w);
                *(uint2*)(Whi + j * ST + k4) = make_uint2(packbf(w.x, w.y), packbf(w.z, w.w));
                *(uint2*)(Wlo + j * ST + k4) =
                    make_uint2(packbf(w.x - h0, w.y - h1), packbf(w.z - h2, w.w - h3));
            }
            if (half == 0 && t < 128) sb[t] = Bs[L][t];
            __syncthreads();

            // GEMM this half: 8 nt tiles -> acc[half*8 + 2p(+1)]
            #pragma unroll
            for (int kt = 0; kt < 8; kt++) {
                const uint32_t kb = kt * 32;
                uint32_t ah[4], al[4];
                ldsm4(ah, aHiB + kb);
                ldsm4(al, aLoB + kb);
                #pragma unroll
                for (int p = 0; p < 4; p++) {
                    uint32_t bh[4], bl[4];
                    const uint32_t po = (uint32_t)(p * 16 * ST * 2) + kb;
                    ldsm4(bh, wHiB + po);
                    ldsm4(bl, wLoB + po);
                    float* c0 = acc[half * 8 + 2 * p];
                    float* c1 = acc[half * 8 + 2 * p + 1];
                    mma_bf16(c0, ah[0], ah[1], ah[2], ah[3], bh[0], bh[1]);
                    mma_bf16(c0, ah[0], ah[1], ah[2], ah[3], bl[0], bl[1]);
                    mma_bf16(c0, al[0], al[1], al[2], al[3], bh[0], bh[1]);
                    mma_bf16(c1, ah[0], ah[1], ah[2], ah[3], bh[2], bh[3]);
                    mma_bf16(c1, ah[0], ah[1], ah[2], ah[3], bl[2], bl[3]);
                    mma_bf16(c1, al[0], al[1], al[2], al[3], bh[2], bh[3]);
                }
            }
            __syncthreads();   // done reading W half before restage / A before overwrite
        }

        if (L < 3) {
            // ---- epilogue: bias + lrelu + split back into A ----
            #pragma unroll
            for (int q = 0; q < 16; q++) {
                int c = (q >> 3) * 64 + (q & 7) * 8 + 2 * tig;
                float v0 = lrelu(acc[q][0] + sb[c]);
                float v1 = lrelu(acc[q][1] + sb[c + 1]);
                float v2 = lrelu(acc[q][2] + sb[c]);
                float v3 = lrelu(acc[q][3] + sb[c + 1]);
                float h0 = bf16rt(v0), h1 = bf16rt(v1), h2 = bf16rt(v2), h3 = bf16rt(v3);
                *(uint32_t*)(Ahi + (r0 + gid) * ST + c)     = packbf(v0, v1);
                *(uint32_t*)(Ahi + (r0 + gid + 8) * ST + c) = packbf(v2, v3);
                *(uint32_t*)(Alo + (r0 + gid) * ST + c)     = packbf(v0 - h0, v1 - h1);
                *(uint32_t*)(Alo + (r0 + gid + 8) * ST + c) = packbf(v2 - h2, v3 - h3);
            }
            __syncthreads();
        } else {
            // ---- last hidden layer: fold into ff dot products ----
            float p0 = 0.f, p1 = 0.f, q0 = 0.f, q1 = 0.f;
            #pragma unroll
            for (int q = 0; q < 16; q++) {
                int c = (q >> 3) * 64 + (q & 7) * 8 + 2 * tig;
                float v0 = lrelu(acc[q][0] + sb[c]);
                float v1 = lrelu(acc[q][1] + sb[c + 1]);
                float v2 = lrelu(acc[q][2] + sb[c]);
                float v3 = lrelu(acc[q][3] + sb[c + 1]);
                p0 = fmaf(v0, sff[c], fmaf(v1, sff[c + 1], p0));
                p1 = fmaf(v0, sff[128 + c], fmaf(v1, sff[129 + c], p1));
                q0 = fmaf(v2, sff[c], fmaf(v3, sff[c + 1], q0));
                q1 = fmaf(v2, sff[128 + c], fmaf(v3, sff[129 + c], q1));
            }
            #pragma unroll
            for (int m = 1; m < 4; m <<= 1) {
                p0 += __shfl_xor_sync(0xFFFFFFFFu, p0, m);
                p1 += __shfl_xor_sync(0xFFFFFFFFu, p1, m);
                q0 += __shfl_xor_sync(0xFFFFFFFFu, q0, m);
                q1 += __shfl_xor_sync(0xFFFFFFFFu, q1, m);
            }
            if (tig == 0) {
                sp0[r0 + gid] = p0;  sp1[r0 + gid] = p1;
                sp0[r0 + gid + 8] = q0;  sp1[r0 + gid + 8] = q1;
            }
            __syncthreads();
        }
    }

    // ---- final projection ----
    if (t < 128) {
        int gi = base + t;
        if (gi < n) {
            float fh0 = sff[256] + sp0[t];
            float fh1 = sff[257] + sp1[t];
            float g0 = g_gradV[2 * gi], g1 = g_gradV[2 * gi + 1];
            float V  = g_V[gi];
            float vn  = g0 * g0 + g1 * g1;
            float num = fh0 * g0 + fh1 * g1 + ALPHAC * V;
            float fm  = (num > 0.f ? num : 0.f) / (vn + EPSC);
            out[2 * gi]     = fh0 - g0 * fm;
            out[2 * gi + 1] = fh1 - g1 * fm;
        }
    }
}

// ============================================================================
extern "C" void kernel_launch(void* const* d_in, const int* in_sizes, int n_in,
                              void* d_out, int out_size)
{
    const float* X   = (const float*)d_in[0];
    const float* Xs  = (const float*)d_in[1];
    const float* Vl1 = (const float*)d_in[2];
    const float* V2x = (const float*)d_in[3];
    const float* V2z = (const float*)d_in[4];
    const float* V3x = (const float*)d_in[5];
    const float* V3z = (const float*)d_in[6];
    const float* Vfx = (const float*)d_in[7];
    const float* Vfz = (const float*)d_in[8];
    const float* f1w = (const float*)d_in[9];
    const float* f1b = (const float*)d_in[10];
    const float* f2w = (const float*)d_in[11];
    const float* f2b = (const float*)d_in[12];
    const float* f3w = (const float*)d_in[13];
    const float* f3b = (const float*)d_in[14];
    const float* f4w = (const float*)d_in[15];
    const float* f4b = (const float*)d_in[16];
    const float* f5w = (const float*)d_in[17];
    const float* f5b = (const float*)d_in[18];
    const float* ffw = (const float*)d_in[19];
    const float* ffb = (const float*)d_in[20];

    int n = in_sizes[0] / 2;

    cudaFuncSetAttribute(vnet_kernel, cudaFuncAttributeMaxDynamicSharedMemorySize, SMEMA_BYTES);
    cudaFuncSetAttribute(fhat_kernel, cudaFuncAttributeMaxDynamicSharedMemorySize, SMEMB_BYTES);

    vnet_kernel<<<(n + PA - 1) / PA, TA, SMEMA_BYTES>>>(
        X, Xs, Vl1, V2x, V2z, V3x, V3z, Vfx, Vfz, n);

    fhat_kernel<<<(n + 127) / 128, TB, SMEMB_BYTES>>>(
        X, f1w, f1b, f2w, f2b, f3w, f3b, f4w, f4b, f5w, f5b, ffw, ffb,
        (float*)d_out, n);
}